// round 9
// baseline (speedup 1.0000x reference)
#include <cuda_runtime.h>
#include <cuda_bf16.h>
#include <mma.h>
#include <cstdint>

using namespace nvcuda;

#define DEVINL __device__ __forceinline__

static constexpr int B_ = 8;
static constexpr int L_ = 2048;
static constexpr int D_ = 128;
static constexpr int NT = 512;    // threads per CTA (16 warps)

// Padded strides (elements)
static constexpr int LDB = 136;   // bf16 tiles: 272B rows
static constexpr int LDC = 132;   // f32 staging rows

static constexpr int TILE_BYTES = 128 * LDB * 2;   // 34816

// ---- scores kernel smem: 6 tile slots (208896 B) ----
static constexpr int T0 = 0;
static constexpr int T1 = T0 + TILE_BYTES;
static constexpr int T2 = T1 + TILE_BYTES;
static constexpr int T3 = T2 + TILE_BYTES;
static constexpr int T4 = T3 + TILE_BYTES;
static constexpr int T5 = T4 + TILE_BYTES;
static constexpr int S_SMEM = T5 + TILE_BYTES;         // 208896

// ---- proj kernel smem ----
static constexpr int P_BIAS = 0;                       // 512B
static constexpr int P_XH = 1024;
static constexpr int P_XL = P_XH + TILE_BYTES;
static constexpr int P_WH = P_XL + TILE_BYTES;
static constexpr int P_WL = P_WH + TILE_BYTES;
static constexpr int P_SMEM = P_WL + TILE_BYTES;       // 140288
static constexpr int P_C = P_XH;                       // overlay: 67584 <= 69632

// ---------------------------------------------------------------------------
// Scratch: projection outputs hi/lo (p: qm=0, km=1, qs=2, ks=3)
// ---------------------------------------------------------------------------
__device__ __align__(16) __nv_bfloat16 g_ph[4][(size_t)B_ * L_ * D_];
__device__ __align__(16) __nv_bfloat16 g_pl[4][(size_t)B_ * L_ * D_];

// ---------------------------------------------------------------------------
DEVINL void cp_async16(uint32_t dst, const void* src) {
    asm volatile("cp.async.cg.shared.global [%0], [%1], 16;" :: "r"(dst), "l"(src) : "memory");
}
DEVINL void cp_commit() { asm volatile("cp.async.commit_group;" ::: "memory"); }
template <int N>
DEVINL void cp_wait_group() { asm volatile("cp.async.wait_group %0;" :: "n"(N) : "memory"); }
DEVINL uint32_t smem_u32(const void* p) {
    uint32_t a;
    asm("{ .reg .u64 t; cvta.to.shared.u64 t, %1; cvt.u32.u64 %0, t; }" : "=r"(a) : "l"(p));
    return a;
}

DEVINL uint32_t pack2(__nv_bfloat16 a, __nv_bfloat16 b) {
    return (uint32_t)__bfloat16_as_ushort(a) | ((uint32_t)__bfloat16_as_ushort(b) << 16);
}
DEVINL void split2(float a, float b, uint32_t& h, uint32_t& l) {
    __nv_bfloat16 ha = __float2bfloat16_rn(a);
    __nv_bfloat16 hb = __float2bfloat16_rn(b);
    __nv_bfloat16 la = __float2bfloat16_rn(a - __bfloat162float(ha));
    __nv_bfloat16 lb = __float2bfloat16_rn(b - __bfloat162float(hb));
    h = pack2(ha, hb);
    l = pack2(la, lb);
}

// accurate tanh: 1 EX2 + 1 fast div (2 MUFU lane-ops), rel err ~3e-6
DEVINL float tanh_fast(float x) {
    x = fminf(fmaxf(x, -15.0f), 15.0f);
    float e = __expf(2.0f * x);
    return __fdividef(e - 1.0f, e + 1.0f);
}

// Load 128x128 bf16 tile (row-major 256B rows) into padded smem (272B rows).
DEVINL void load_tile_cp(uint32_t dst, const __nv_bfloat16* src, int tid) {
    const char* s = reinterpret_cast<const char*>(src);
#pragma unroll
    for (int i = 0; i < 2048 / NT; i++) {
        int idx = i * NT + tid;
        int r = idx >> 4, c = idx & 15;
        cp_async16(dst + r * 272 + c * 16, s + r * 256 + c * 16);
    }
}

typedef wmma::fragment<wmma::matrix_a, 16, 16, 16, __nv_bfloat16, wmma::row_major> FragA;
typedef wmma::fragment<wmma::matrix_b, 16, 16, 16, __nv_bfloat16, wmma::col_major> FragBc;
typedef wmma::fragment<wmma::matrix_b, 16, 16, 16, __nv_bfloat16, wmma::row_major> FragBr;
typedef wmma::fragment<wmma::accumulator, 16, 16, 16, float> FragC;

// ---------------------------------------------------------------------------
// Kernel 1: projections Y = X @ W + b.  CTA: 128-row X tile, one of 4 p's.
// 16 warps in 4x4 grid, each 32x32 out. Fragment-reuse k-loop.
// ---------------------------------------------------------------------------
__global__ __launch_bounds__(NT, 1)
void proj_kernel(const float* __restrict__ query, const float* __restrict__ key,
                 const float* __restrict__ wqm, const float* __restrict__ bqm,
                 const float* __restrict__ wkm, const float* __restrict__ bkm,
                 const float* __restrict__ wqs, const float* __restrict__ bqs,
                 const float* __restrict__ wks, const float* __restrict__ bks) {
    extern __shared__ __align__(16) char smem[];
    const int tid = threadIdx.x, wid = tid >> 5;
    const int p = blockIdx.y;
    const int m0 = blockIdx.x * 128;

    const float* src  = (p & 1) ? key : query;
    const float* W    = (p == 0) ? wqm : (p == 1) ? wkm : (p == 2) ? wqs : wks;
    const float* bias = (p == 0) ? bqm : (p == 1) ? bkm : (p == 2) ? bqs : bks;

    float* sbias = reinterpret_cast<float*>(smem + P_BIAS);
    if (tid < 128) sbias[tid] = bias[tid];

    // X (128x128) and W (128x128): f32 load -> hi/lo split -> padded smem
#pragma unroll
    for (int i = 0; i < 4; i++) {
        int idx = i * NT + tid;
        int r = idx >> 4, c = idx & 15;
        {
            const float* sp = src + (size_t)(m0 + r) * D_ + c * 8;
            float4 v0 = *reinterpret_cast<const float4*>(sp);
            float4 v1 = *reinterpret_cast<const float4*>(sp + 4);
            uint4 H, Lo;
            split2(v0.x, v0.y, H.x, Lo.x);
            split2(v0.z, v0.w, H.y, Lo.y);
            split2(v1.x, v1.y, H.z, Lo.z);
            split2(v1.z, v1.w, H.w, Lo.w);
            *reinterpret_cast<uint4*>(smem + P_XH + r * 272 + c * 16) = H;
            *reinterpret_cast<uint4*>(smem + P_XL + r * 272 + c * 16) = Lo;
        }
        {
            const float* sp = W + (size_t)r * D_ + c * 8;
            float4 v0 = *reinterpret_cast<const float4*>(sp);
            float4 v1 = *reinterpret_cast<const float4*>(sp + 4);
            uint4 H, Lo;
            split2(v0.x, v0.y, H.x, Lo.x);
            split2(v0.z, v0.w, H.y, Lo.y);
            split2(v1.x, v1.y, H.z, Lo.z);
            split2(v1.z, v1.w, H.w, Lo.w);
            *reinterpret_cast<uint4*>(smem + P_WH + r * 272 + c * 16) = H;
            *reinterpret_cast<uint4*>(smem + P_WL + r * 272 + c * 16) = Lo;
        }
    }
    __syncthreads();

    const int wm = wid & 3, wn = wid >> 2;   // 4 x 4 warp grid -> 32 x 32 each
    const __nv_bfloat16* sXh = reinterpret_cast<const __nv_bfloat16*>(smem + P_XH);
    const __nv_bfloat16* sXl = reinterpret_cast<const __nv_bfloat16*>(smem + P_XL);
    const __nv_bfloat16* sWh = reinterpret_cast<const __nv_bfloat16*>(smem + P_WH);
    const __nv_bfloat16* sWl = reinterpret_cast<const __nv_bfloat16*>(smem + P_WL);

    FragC acc[2][2];
#pragma unroll
    for (int i = 0; i < 2; i++)
#pragma unroll
        for (int j = 0; j < 2; j++) wmma::fill_fragment(acc[i][j], 0.0f);

#pragma unroll
    for (int k = 0; k < 8; k++) {
        FragA ah[2], al[2];
        wmma::load_matrix_sync(ah[0], sXh + (wm * 32 + 0) * LDB + k * 16, LDB);
        wmma::load_matrix_sync(ah[1], sXh + (wm * 32 + 16) * LDB + k * 16, LDB);
        wmma::load_matrix_sync(al[0], sXl + (wm * 32 + 0) * LDB + k * 16, LDB);
        wmma::load_matrix_sync(al[1], sXl + (wm * 32 + 16) * LDB + k * 16, LDB);
#pragma unroll
        for (int j = 0; j < 2; j++) {
            FragBr bh, bl;
            wmma::load_matrix_sync(bh, sWh + (k * 16) * LDB + (wn * 32 + j * 16), LDB);
            wmma::load_matrix_sync(bl, sWl + (k * 16) * LDB + (wn * 32 + j * 16), LDB);
            wmma::mma_sync(acc[0][j], ah[0], bh, acc[0][j]);
            wmma::mma_sync(acc[1][j], ah[1], bh, acc[1][j]);
            wmma::mma_sync(acc[0][j], al[0], bh, acc[0][j]);
            wmma::mma_sync(acc[1][j], al[1], bh, acc[1][j]);
            wmma::mma_sync(acc[0][j], ah[0], bl, acc[0][j]);
            wmma::mma_sync(acc[1][j], ah[1], bl, acc[1][j]);
        }
    }
    __syncthreads();

    // C -> smem overlay (X area no longer needed)
    float* Cs = reinterpret_cast<float*>(smem + P_C);
#pragma unroll
    for (int i = 0; i < 2; i++)
#pragma unroll
        for (int j = 0; j < 2; j++)
            wmma::store_matrix_sync(Cs + (wm * 32 + i * 16) * LDC + (wn * 32 + j * 16),
                                    acc[i][j], LDC, wmma::mem_row_major);
    __syncthreads();

    // epilogue: + bias, hi/lo split, store scratch
#pragma unroll
    for (int i = 0; i < 8; i++) {
        int u = i * NT + tid;
        int r = u >> 5, c4 = (u & 31) << 2;
        float4 v = *reinterpret_cast<const float4*>(Cs + r * LDC + c4);
        v.x += sbias[c4 + 0];
        v.y += sbias[c4 + 1];
        v.z += sbias[c4 + 2];
        v.w += sbias[c4 + 3];
        uint32_t h01, l01, h23, l23;
        split2(v.x, v.y, h01, l01);
        split2(v.z, v.w, h23, l23);
        size_t o = (size_t)(m0 + r) * D_ + c4;
        *reinterpret_cast<uint2*>(g_ph[p] + o) = make_uint2(h01, h23);
        *reinterpret_cast<uint2*>(g_pl[p] + o) = make_uint2(l01, l23);
    }
}

// ---------------------------------------------------------------------------
// Kernel 2: scores. CTA = 128x128 S tile, both phases, 16 warps (4x4 grid,
// 32x32 out each). 6-slot pipeline:
//   g0: K0 -> T2,T3
//   mask staged in T0/T1 -> per-lane bitmask (once)
//   g1: Q0 -> T0,T1;  g2: K1 -> T4,T5 (prefetch)
//   phase0 MMA; then g3: Q1 -> T0,T1 overlapping phase-0 epilogue
//   phase1 MMA + epilogue
// ---------------------------------------------------------------------------
__global__ __launch_bounds__(NT, 1)
void scores_kernel(const int* __restrict__ mask, float* __restrict__ out) {
    extern __shared__ __align__(16) char smem[];
    const int tid = threadIdx.x, wid = tid >> 5;
    const int nb0 = blockIdx.x * 128;
    const int mb0 = blockIdx.y * 128;
    const int b = blockIdx.z;
    const uint32_t sbase = smem_u32(smem);
    const int wm = wid & 3, wn = wid >> 2;   // 4 x 4 -> 32 x 32 per warp
    const float inv_sqrt_d = 0.08838834764831845f;

    const size_t qoff = ((size_t)b * L_ + mb0) * D_;
    const size_t koff = ((size_t)b * L_ + nb0) * D_;

    // g0: K0 tiles
    load_tile_cp(sbase + T2, g_ph[1] + koff, tid);
    load_tile_cp(sbase + T3, g_pl[1] + koff, tid);
    cp_commit();

    // mask -> f32 staging (T0/T1 overlay) -> per-lane bitmask
    float* Ms = reinterpret_cast<float*>(smem + T0);
#pragma unroll
    for (int i = 0; i < 8; i++) {
        int u = i * NT + tid;
        int r = u >> 5, c4 = (u & 31) << 2;
        int4 mm = *reinterpret_cast<const int4*>(
            mask + ((size_t)b * L_ + mb0 + r) * L_ + nb0 + c4);
        float4 f;
        f.x = mm.x ? 1.0f : 0.0f;
        f.y = mm.y ? 1.0f : 0.0f;
        f.z = mm.z ? 1.0f : 0.0f;
        f.w = mm.w ? 1.0f : 0.0f;
        *reinterpret_cast<float4*>(Ms + r * LDC + c4) = f;
    }
    __syncthreads();

    uint32_t mbits = 0;
#pragma unroll
    for (int i = 0; i < 2; i++)
#pragma unroll
        for (int j = 0; j < 2; j++) {
            FragC mf;
            wmma::load_matrix_sync(mf, Ms + (wm * 32 + i * 16) * LDC + (wn * 32 + j * 16),
                                   LDC, wmma::mem_row_major);
#pragma unroll
            for (int e = 0; e < 8; e++)
                mbits |= (mf.x[e] != 0.0f ? 1u : 0u) << ((i * 2 + j) * 8 + e);
        }
    __syncthreads();   // staging consumed; T0/T1 reusable

    // g1: Q0 tiles; g2: K1 prefetch
    load_tile_cp(sbase + T0, g_ph[0] + qoff, tid);
    load_tile_cp(sbase + T1, g_pl[0] + qoff, tid);
    cp_commit();
    load_tile_cp(sbase + T4, g_ph[3] + koff, tid);
    load_tile_cp(sbase + T5, g_pl[3] + koff, tid);
    cp_commit();

    cp_wait_group<1>();   // g0 + g1 done; g2 may still fly
    __syncthreads();

    const __nv_bfloat16* sQh = reinterpret_cast<const __nv_bfloat16*>(smem + T0);
    const __nv_bfloat16* sQl = reinterpret_cast<const __nv_bfloat16*>(smem + T1);

    for (int phase = 0; phase < 2; phase++) {
        const __nv_bfloat16* Kh = reinterpret_cast<const __nv_bfloat16*>(
            smem + (phase ? T4 : T2));
        const __nv_bfloat16* Kl = reinterpret_cast<const __nv_bfloat16*>(
            smem + (phase ? T5 : T3));

        FragC acc[2][2];
#pragma unroll
        for (int i = 0; i < 2; i++)
#pragma unroll
            for (int j = 0; j < 2; j++) wmma::fill_fragment(acc[i][j], 0.0f);

#pragma unroll
        for (int k = 0; k < 8; k++) {
            FragA ah[2], al[2];
            wmma::load_matrix_sync(ah[0], sQh + (wm * 32 + 0) * LDB + k * 16, LDB);
            wmma::load_matrix_sync(ah[1], sQh + (wm * 32 + 16) * LDB + k * 16, LDB);
            wmma::load_matrix_sync(al[0], sQl + (wm * 32 + 0) * LDB + k * 16, LDB);
            wmma::load_matrix_sync(al[1], sQl + (wm * 32 + 16) * LDB + k * 16, LDB);
#pragma unroll
            for (int j = 0; j < 2; j++) {
                FragBc bh, bl;   // K row-major [n][k] == col-major (k,n)
                wmma::load_matrix_sync(bh, Kh + (wn * 32 + j * 16) * LDB + k * 16, LDB);
                wmma::load_matrix_sync(bl, Kl + (wn * 32 + j * 16) * LDB + k * 16, LDB);
                wmma::mma_sync(acc[0][j], ah[0], bh, acc[0][j]);
                wmma::mma_sync(acc[1][j], ah[1], bh, acc[1][j]);
                wmma::mma_sync(acc[0][j], al[0], bh, acc[0][j]);
                wmma::mma_sync(acc[1][j], al[1], bh, acc[1][j]);
                wmma::mma_sync(acc[0][j], ah[0], bl, acc[0][j]);
                wmma::mma_sync(acc[1][j], ah[1], bl, acc[1][j]);
            }
        }

        if (phase == 0) {
            __syncthreads();   // Q0 fully consumed by all warps
            // g3: Q1 -> T0,T1, overlapping phase-0 epilogue
            load_tile_cp(sbase + T0, g_ph[2] + qoff, tid);
            load_tile_cp(sbase + T1, g_pl[2] + qoff, tid);
            cp_commit();
        }

        // register epilogue: scale -> tanh -> mask select -> store to global
        float* obase = out + (size_t)phase * B_ * L_ * L_ + (size_t)b * L_ * L_;
#pragma unroll
        for (int i = 0; i < 2; i++) {
#pragma unroll
            for (int j = 0; j < 2; j++) {
                int r0 = wm * 32 + i * 16, c0 = wn * 32 + j * 16;
#pragma unroll
                for (int e = 0; e < 8; e++) {
                    float t = tanh_fast(acc[i][j].x[e] * inv_sqrt_d);
                    bool m = (mbits >> ((i * 2 + j) * 8 + e)) & 1u;
                    acc[i][j].x[e] = (phase == 0)
                        ? (m ? fmaf(0.5f, t, 0.5f) : 0.0f)
                        : (m ? fmaf(4.0f, t, -6.0f) : -10.0f);
                }
                wmma::store_matrix_sync(obase + (size_t)(mb0 + r0) * L_ + (nb0 + c0),
                                        acc[i][j], L_, wmma::mem_row_major);
            }
        }

        if (phase == 0) {
            cp_wait_group<0>();   // g2 (K1) + g3 (Q1) complete
            __syncthreads();
        }
    }
}

// ---------------------------------------------------------------------------
extern "C" void kernel_launch(void* const* d_in, const int* in_sizes, int n_in,
                              void* d_out, int out_size) {
    const float* query = (const float*)d_in[0];
    const float* key   = (const float*)d_in[1];
    const int*   mask  = (const int*)d_in[2];
    const float* wqm = (const float*)d_in[3];
    const float* bqm = (const float*)d_in[4];
    const float* wkm = (const float*)d_in[5];
    const float* bkm = (const float*)d_in[6];
    const float* wqs = (const float*)d_in[7];
    const float* bqs = (const float*)d_in[8];
    const float* wks = (const float*)d_in[9];
    const float* bks = (const float*)d_in[10];
    float* out = (float*)d_out;

    cudaFuncSetAttribute(proj_kernel, cudaFuncAttributeMaxDynamicSharedMemorySize, P_SMEM);
    cudaFuncSetAttribute(scores_kernel, cudaFuncAttributeMaxDynamicSharedMemorySize, S_SMEM);

    proj_kernel<<<dim3((B_ * L_) / 128, 4), NT, P_SMEM>>>(
        query, key, wqm, bqm, wkm, bkm, wqs, bqs, wks, bks);
    scores_kernel<<<dim3(L_ / 128, L_ / 128, B_), NT, S_SMEM>>>(mask, out);
}

// round 10
// speedup vs baseline: 1.2673x; 1.2673x over previous
#include <cuda_runtime.h>
#include <cuda_bf16.h>
#include <cuda_fp16.h>
#include <mma.h>
#include <cstdint>

using namespace nvcuda;

#define DEVINL __device__ __forceinline__

static constexpr int B_ = 8;
static constexpr int L_ = 2048;
static constexpr int D_ = 128;
static constexpr int NT = 512;    // threads per CTA (16 warps)

// Padded strides (elements)
static constexpr int LDB = 136;   // 16-bit tiles: 272B rows
static constexpr int LDC = 132;   // f32 staging rows

static constexpr int TILE_BYTES = 128 * LDB * 2;   // 34816

// ---- scores kernel smem: 6 tile slots (208896 B) ----
// S0=Q0h S1=Q0l S2=K0h S3=Q1h S4=Q1l S5=K1h  (fp16)
// mask f32 staging overlays S4..S5 before their loads (67584 <= 69632)
static constexpr int S0 = 0;
static constexpr int S1 = S0 + TILE_BYTES;
static constexpr int S2 = S1 + TILE_BYTES;
static constexpr int S3 = S2 + TILE_BYTES;
static constexpr int S4 = S3 + TILE_BYTES;
static constexpr int S5 = S4 + TILE_BYTES;
static constexpr int S_SMEM = S5 + TILE_BYTES;         // 208896

// ---- proj kernel smem (bf16 MMA tiles) ----
static constexpr int P_BIAS = 0;                       // 512B
static constexpr int P_XH = 1024;
static constexpr int P_XL = P_XH + TILE_BYTES;
static constexpr int P_WH = P_XL + TILE_BYTES;
static constexpr int P_WL = P_WH + TILE_BYTES;
static constexpr int P_SMEM = P_WL + TILE_BYTES;       // 140288
static constexpr int P_C = P_XH;                       // overlay: 67584 <= 69632

// ---------------------------------------------------------------------------
// Scratch: projection outputs fp16 hi/lo (p: qm=0, km=1, qs=2, ks=3)
// ---------------------------------------------------------------------------
__device__ __align__(16) __half g_ph[4][(size_t)B_ * L_ * D_];
__device__ __align__(16) __half g_pl[4][(size_t)B_ * L_ * D_];

// ---------------------------------------------------------------------------
DEVINL void cp_async16(uint32_t dst, const void* src) {
    asm volatile("cp.async.cg.shared.global [%0], [%1], 16;" :: "r"(dst), "l"(src) : "memory");
}
DEVINL void cp_commit() { asm volatile("cp.async.commit_group;" ::: "memory"); }
template <int N>
DEVINL void cp_wait_group() { asm volatile("cp.async.wait_group %0;" :: "n"(N) : "memory"); }
DEVINL uint32_t smem_u32(const void* p) {
    uint32_t a;
    asm("{ .reg .u64 t; cvta.to.shared.u64 t, %1; cvt.u32.u64 %0, t; }" : "=r"(a) : "l"(p));
    return a;
}

// bf16 split (proj-internal MMA tiles)
DEVINL uint32_t pack2b(__nv_bfloat16 a, __nv_bfloat16 b) {
    return (uint32_t)__bfloat16_as_ushort(a) | ((uint32_t)__bfloat16_as_ushort(b) << 16);
}
DEVINL void split2(float a, float b, uint32_t& h, uint32_t& l) {
    __nv_bfloat16 ha = __float2bfloat16_rn(a);
    __nv_bfloat16 hb = __float2bfloat16_rn(b);
    __nv_bfloat16 la = __float2bfloat16_rn(a - __bfloat162float(ha));
    __nv_bfloat16 lb = __float2bfloat16_rn(b - __bfloat162float(hb));
    h = pack2b(ha, hb);
    l = pack2b(la, lb);
}
// fp16 split (scratch)
DEVINL uint32_t pack2h(__half a, __half b) {
    return (uint32_t)__half_as_ushort(a) | ((uint32_t)__half_as_ushort(b) << 16);
}
DEVINL void split2h(float a, float b, uint32_t& h, uint32_t& l) {
    __half ha = __float2half_rn(a);
    __half hb = __float2half_rn(b);
    __half la = __float2half_rn(a - __half2float(ha));
    __half lb = __float2half_rn(b - __half2float(hb));
    h = pack2h(ha, hb);
    l = pack2h(la, lb);
}

// accurate tanh: 1 EX2 + 1 fast div (2 MUFU lane-ops), rel err ~3e-6
DEVINL float tanh_fast(float x) {
    x = fminf(fmaxf(x, -15.0f), 15.0f);
    float e = __expf(2.0f * x);
    return __fdividef(e - 1.0f, e + 1.0f);
}

// Load 128x128 16-bit tile (row-major 256B rows) into padded smem (272B rows).
DEVINL void load_tile_cp(uint32_t dst, const void* src, int tid) {
    const char* s = reinterpret_cast<const char*>(src);
#pragma unroll
    for (int i = 0; i < 2048 / NT; i++) {
        int idx = i * NT + tid;
        int r = idx >> 4, c = idx & 15;
        cp_async16(dst + r * 272 + c * 16, s + r * 256 + c * 16);
    }
}

typedef wmma::fragment<wmma::matrix_a, 16, 16, 16, __nv_bfloat16, wmma::row_major> FragAb;
typedef wmma::fragment<wmma::matrix_b, 16, 16, 16, __nv_bfloat16, wmma::row_major> FragBrb;
typedef wmma::fragment<wmma::matrix_a, 16, 16, 16, __half, wmma::row_major> FragAh;
typedef wmma::fragment<wmma::matrix_b, 16, 16, 16, __half, wmma::col_major> FragBch;
typedef wmma::fragment<wmma::accumulator, 16, 16, 16, float> FragC;

// ---------------------------------------------------------------------------
// Kernel 1: projections Y = X @ W + b.  3-pass bf16 MMA (error ~2^-16),
// output written as fp16 hi/lo scratch. 16 warps in 4x4 grid, 32x32 each.
// ---------------------------------------------------------------------------
__global__ __launch_bounds__(NT, 1)
void proj_kernel(const float* __restrict__ query, const float* __restrict__ key,
                 const float* __restrict__ wqm, const float* __restrict__ bqm,
                 const float* __restrict__ wkm, const float* __restrict__ bkm,
                 const float* __restrict__ wqs, const float* __restrict__ bqs,
                 const float* __restrict__ wks, const float* __restrict__ bks) {
    extern __shared__ __align__(16) char smem[];
    const int tid = threadIdx.x, wid = tid >> 5;
    const int p = blockIdx.y;
    const int m0 = blockIdx.x * 128;

    const float* src  = (p & 1) ? key : query;
    const float* W    = (p == 0) ? wqm : (p == 1) ? wkm : (p == 2) ? wqs : wks;
    const float* bias = (p == 0) ? bqm : (p == 1) ? bkm : (p == 2) ? bqs : bks;

    float* sbias = reinterpret_cast<float*>(smem + P_BIAS);
    if (tid < 128) sbias[tid] = bias[tid];

    // X (128x128) and W (128x128): f32 load -> bf16 hi/lo split -> padded smem
#pragma unroll
    for (int i = 0; i < 4; i++) {
        int idx = i * NT + tid;
        int r = idx >> 4, c = idx & 15;
        {
            const float* sp = src + (size_t)(m0 + r) * D_ + c * 8;
            float4 v0 = *reinterpret_cast<const float4*>(sp);
            float4 v1 = *reinterpret_cast<const float4*>(sp + 4);
            uint4 H, Lo;
            split2(v0.x, v0.y, H.x, Lo.x);
            split2(v0.z, v0.w, H.y, Lo.y);
            split2(v1.x, v1.y, H.z, Lo.z);
            split2(v1.z, v1.w, H.w, Lo.w);
            *reinterpret_cast<uint4*>(smem + P_XH + r * 272 + c * 16) = H;
            *reinterpret_cast<uint4*>(smem + P_XL + r * 272 + c * 16) = Lo;
        }
        {
            const float* sp = W + (size_t)r * D_ + c * 8;
            float4 v0 = *reinterpret_cast<const float4*>(sp);
            float4 v1 = *reinterpret_cast<const float4*>(sp + 4);
            uint4 H, Lo;
            split2(v0.x, v0.y, H.x, Lo.x);
            split2(v0.z, v0.w, H.y, Lo.y);
            split2(v1.x, v1.y, H.z, Lo.z);
            split2(v1.z, v1.w, H.w, Lo.w);
            *reinterpret_cast<uint4*>(smem + P_WH + r * 272 + c * 16) = H;
            *reinterpret_cast<uint4*>(smem + P_WL + r * 272 + c * 16) = Lo;
        }
    }
    __syncthreads();

    const int wm = wid & 3, wn = wid >> 2;   // 4 x 4 warp grid -> 32 x 32 each
    const __nv_bfloat16* sXh = reinterpret_cast<const __nv_bfloat16*>(smem + P_XH);
    const __nv_bfloat16* sXl = reinterpret_cast<const __nv_bfloat16*>(smem + P_XL);
    const __nv_bfloat16* sWh = reinterpret_cast<const __nv_bfloat16*>(smem + P_WH);
    const __nv_bfloat16* sWl = reinterpret_cast<const __nv_bfloat16*>(smem + P_WL);

    FragC acc[2][2];
#pragma unroll
    for (int i = 0; i < 2; i++)
#pragma unroll
        for (int j = 0; j < 2; j++) wmma::fill_fragment(acc[i][j], 0.0f);

#pragma unroll
    for (int k = 0; k < 8; k++) {
        FragAb ah[2], al[2];
        wmma::load_matrix_sync(ah[0], sXh + (wm * 32 + 0) * LDB + k * 16, LDB);
        wmma::load_matrix_sync(ah[1], sXh + (wm * 32 + 16) * LDB + k * 16, LDB);
        wmma::load_matrix_sync(al[0], sXl + (wm * 32 + 0) * LDB + k * 16, LDB);
        wmma::load_matrix_sync(al[1], sXl + (wm * 32 + 16) * LDB + k * 16, LDB);
#pragma unroll
        for (int j = 0; j < 2; j++) {
            FragBrb bh, bl;
            wmma::load_matrix_sync(bh, sWh + (k * 16) * LDB + (wn * 32 + j * 16), LDB);
            wmma::load_matrix_sync(bl, sWl + (k * 16) * LDB + (wn * 32 + j * 16), LDB);
            wmma::mma_sync(acc[0][j], ah[0], bh, acc[0][j]);
            wmma::mma_sync(acc[1][j], ah[1], bh, acc[1][j]);
            wmma::mma_sync(acc[0][j], al[0], bh, acc[0][j]);
            wmma::mma_sync(acc[1][j], al[1], bh, acc[1][j]);
            wmma::mma_sync(acc[0][j], ah[0], bl, acc[0][j]);
            wmma::mma_sync(acc[1][j], ah[1], bl, acc[1][j]);
        }
    }
    __syncthreads();

    // C -> smem overlay (X area no longer needed)
    float* Cs = reinterpret_cast<float*>(smem + P_C);
#pragma unroll
    for (int i = 0; i < 2; i++)
#pragma unroll
        for (int j = 0; j < 2; j++)
            wmma::store_matrix_sync(Cs + (wm * 32 + i * 16) * LDC + (wn * 32 + j * 16),
                                    acc[i][j], LDC, wmma::mem_row_major);
    __syncthreads();

    // epilogue: + bias, fp16 hi/lo split, store scratch
#pragma unroll
    for (int i = 0; i < 8; i++) {
        int u = i * NT + tid;
        int r = u >> 5, c4 = (u & 31) << 2;
        float4 v = *reinterpret_cast<const float4*>(Cs + r * LDC + c4);
        v.x += sbias[c4 + 0];
        v.y += sbias[c4 + 1];
        v.z += sbias[c4 + 2];
        v.w += sbias[c4 + 3];
        uint32_t h01, l01, h23, l23;
        split2h(v.x, v.y, h01, l01);
        split2h(v.z, v.w, h23, l23);
        size_t o = (size_t)(m0 + r) * D_ + c4;
        *reinterpret_cast<uint2*>(g_ph[p] + o) = make_uint2(h01, h23);
        *reinterpret_cast<uint2*>(g_pl[p] + o) = make_uint2(l01, l23);
    }
}

// ---------------------------------------------------------------------------
// Kernel 2: scores. CTA = 128x128 S tile, both phases. fp16 2-pass:
// S = (Qh + Ql) @ Kh^T  (exact in Q; K rounding 2^-11 -> aggregate ~1.5e-4).
// All 6 tiles resident; ONE barrier before MMA0, then barrier-free.
//   g0: S0=Q0h S1=Q0l S2=K0h S3=Q1h
//   mask f32 staged over S4/S5 -> per-lane bitmask
//   g1: S4=Q1l S5=K1h
// ---------------------------------------------------------------------------
__global__ __launch_bounds__(NT, 1)
void scores_kernel(const int* __restrict__ mask, float* __restrict__ out) {
    extern __shared__ __align__(16) char smem[];
    const int tid = threadIdx.x, wid = tid >> 5;
    const int nb0 = blockIdx.x * 128;
    const int mb0 = blockIdx.y * 128;
    const int b = blockIdx.z;
    const uint32_t sbase = smem_u32(smem);
    const int wm = wid & 3, wn = wid >> 2;   // 4 x 4 -> 32 x 32 per warp
    const float inv_sqrt_d = 0.08838834764831845f;

    const size_t qoff = ((size_t)b * L_ + mb0) * D_;
    const size_t koff = ((size_t)b * L_ + nb0) * D_;

    // g0: Q0h, Q0l, K0h, Q1h
    load_tile_cp(sbase + S0, g_ph[0] + qoff, tid);
    load_tile_cp(sbase + S1, g_pl[0] + qoff, tid);
    load_tile_cp(sbase + S2, g_ph[1] + koff, tid);
    load_tile_cp(sbase + S3, g_ph[2] + qoff, tid);
    cp_commit();

    // mask -> f32 staging over S4/S5 -> per-lane bitmask
    float* Ms = reinterpret_cast<float*>(smem + S4);
#pragma unroll
    for (int i = 0; i < 8; i++) {
        int u = i * NT + tid;
        int r = u >> 5, c4 = (u & 31) << 2;
        int4 mm = *reinterpret_cast<const int4*>(
            mask + ((size_t)b * L_ + mb0 + r) * L_ + nb0 + c4);
        float4 f;
        f.x = mm.x ? 1.0f : 0.0f;
        f.y = mm.y ? 1.0f : 0.0f;
        f.z = mm.z ? 1.0f : 0.0f;
        f.w = mm.w ? 1.0f : 0.0f;
        *reinterpret_cast<float4*>(Ms + r * LDC + c4) = f;
    }
    __syncthreads();

    uint32_t mbits = 0;
#pragma unroll
    for (int i = 0; i < 2; i++)
#pragma unroll
        for (int j = 0; j < 2; j++) {
            FragC mf;
            wmma::load_matrix_sync(mf, Ms + (wm * 32 + i * 16) * LDC + (wn * 32 + j * 16),
                                   LDC, wmma::mem_row_major);
#pragma unroll
            for (int e = 0; e < 8; e++)
                mbits |= (mf.x[e] != 0.0f ? 1u : 0u) << ((i * 2 + j) * 8 + e);
        }
    __syncthreads();   // staging consumed; S4/S5 reusable

    // g1: Q1l, K1h
    load_tile_cp(sbase + S4, g_pl[2] + qoff, tid);
    load_tile_cp(sbase + S5, g_ph[3] + koff, tid);
    cp_commit();

    cp_wait_group<0>();
    __syncthreads();   // ONLY barrier before compute; all 6 tiles + bits ready

    for (int phase = 0; phase < 2; phase++) {
        const __half* Qh = reinterpret_cast<const __half*>(smem + (phase ? S3 : S0));
        const __half* Ql = reinterpret_cast<const __half*>(smem + (phase ? S4 : S1));
        const __half* Kh = reinterpret_cast<const __half*>(smem + (phase ? S5 : S2));

        FragC acc[2][2];
#pragma unroll
        for (int i = 0; i < 2; i++)
#pragma unroll
            for (int j = 0; j < 2; j++) wmma::fill_fragment(acc[i][j], 0.0f);

#pragma unroll
        for (int k = 0; k < 8; k++) {
            FragAh ah[2], al[2];
            wmma::load_matrix_sync(ah[0], Qh + (wm * 32 + 0) * LDB + k * 16, LDB);
            wmma::load_matrix_sync(ah[1], Qh + (wm * 32 + 16) * LDB + k * 16, LDB);
            wmma::load_matrix_sync(al[0], Ql + (wm * 32 + 0) * LDB + k * 16, LDB);
            wmma::load_matrix_sync(al[1], Ql + (wm * 32 + 16) * LDB + k * 16, LDB);
#pragma unroll
            for (int j = 0; j < 2; j++) {
                FragBch bh;   // K row-major [n][k] == col-major (k,n)
                wmma::load_matrix_sync(bh, Kh + (wn * 32 + j * 16) * LDB + k * 16, LDB);
                wmma::mma_sync(acc[0][j], ah[0], bh, acc[0][j]);
                wmma::mma_sync(acc[1][j], ah[1], bh, acc[1][j]);
                wmma::mma_sync(acc[0][j], al[0], bh, acc[0][j]);
                wmma::mma_sync(acc[1][j], al[1], bh, acc[1][j]);
            }
        }

        // register epilogue: scale -> tanh -> mask select -> store to global
        float* obase = out + (size_t)phase * B_ * L_ * L_ + (size_t)b * L_ * L_;
#pragma unroll
        for (int i = 0; i < 2; i++) {
#pragma unroll
            for (int j = 0; j < 2; j++) {
                int r0 = wm * 32 + i * 16, c0 = wn * 32 + j * 16;
#pragma unroll
                for (int e = 0; e < 8; e++) {
                    float t = tanh_fast(acc[i][j].x[e] * inv_sqrt_d);
                    bool m = (mbits >> ((i * 2 + j) * 8 + e)) & 1u;
                    acc[i][j].x[e] = (phase == 0)
                        ? (m ? fmaf(0.5f, t, 0.5f) : 0.0f)
                        : (m ? fmaf(4.0f, t, -6.0f) : -10.0f);
                }
                wmma::store_matrix_sync(obase + (size_t)(mb0 + r0) * L_ + (nb0 + c0),
                                        acc[i][j], L_, wmma::mem_row_major);
            }
        }
        // no barrier: phase-1 tiles are distinct slots, all preloaded
    }
}

// ---------------------------------------------------------------------------
extern "C" void kernel_launch(void* const* d_in, const int* in_sizes, int n_in,
                              void* d_out, int out_size) {
    const float* query = (const float*)d_in[0];
    const float* key   = (const float*)d_in[1];
    const int*   mask  = (const int*)d_in[2];
    const float* wqm = (const float*)d_in[3];
    const float* bqm = (const float*)d_in[4];
    const float* wkm = (const float*)d_in[5];
    const float* bkm = (const float*)d_in[6];
    const float* wqs = (const float*)d_in[7];
    const float* bqs = (const float*)d_in[8];
    const float* wks = (const float*)d_in[9];
    const float* bks = (const float*)d_in[10];
    float* out = (float*)d_out;

    cudaFuncSetAttribute(proj_kernel, cudaFuncAttributeMaxDynamicSharedMemorySize, P_SMEM);
    cudaFuncSetAttribute(scores_kernel, cudaFuncAttributeMaxDynamicSharedMemorySize, S_SMEM);

    proj_kernel<<<dim3((B_ * L_) / 128, 4), NT, P_SMEM>>>(
        query, key, wqm, bqm, wkm, bkm, wqs, bqs, wks, bks);
    scores_kernel<<<dim3(L_ / 128, L_ / 128, B_), NT, S_SMEM>>>(mask, out);
}

// round 11
// speedup vs baseline: 1.3165x; 1.0389x over previous
#include <cuda_runtime.h>
#include <cuda_bf16.h>
#include <cuda_fp16.h>
#include <mma.h>
#include <cstdint>

using namespace nvcuda;

#define DEVINL __device__ __forceinline__

static constexpr int B_ = 8;
static constexpr int L_ = 2048;
static constexpr int D_ = 128;
static constexpr int NT = 512;    // scores threads (16 warps)
static constexpr int PT = 256;    // proj threads (8 warps)

// Padded strides (elements)
static constexpr int LDB = 136;   // 16-bit tiles: 272B rows
static constexpr int LDC = 132;   // f32 staging rows

static constexpr int TILE_BYTES = 128 * LDB * 2;    // 34816
static constexpr int TILE64_BYTES = 64 * LDB * 2;   // 17408

// ---- scores kernel smem: 6 tile slots (208896 B), 1 CTA/SM ----
// S0=Q0h S1=Q0l S2=K0h S3=Q1h S4=Q1l S5=K1h  (fp16)
static constexpr int S0 = 0;
static constexpr int S1 = S0 + TILE_BYTES;
static constexpr int S2 = S1 + TILE_BYTES;
static constexpr int S3 = S2 + TILE_BYTES;
static constexpr int S4 = S3 + TILE_BYTES;
static constexpr int S5 = S4 + TILE_BYTES;
static constexpr int S_SMEM = S5 + TILE_BYTES;      // 208896

// ---- proj kernel smem (64-row X tile, 2 CTAs/SM) ----
static constexpr int P_XH = 0;                      // 64-row tile
static constexpr int P_XL = P_XH + TILE64_BYTES;
static constexpr int P_WH = P_XL + TILE64_BYTES;    // 128-row tile
static constexpr int P_WL = P_WH + TILE_BYTES;
static constexpr int P_BIAS = P_WL + TILE_BYTES;    // 104448
static constexpr int P_SMEM = P_BIAS + 512;         // 104960 (x2 = 209920 <= 228KB)
static constexpr int P_C = P_XH;                    // overlay: 64*132*4=33792 <= 34816

// ---------------------------------------------------------------------------
// Scratch: projection outputs fp16 hi/lo (p: qm=0, km=1, qs=2, ks=3)
// ---------------------------------------------------------------------------
__device__ __align__(16) __half g_ph[4][(size_t)B_ * L_ * D_];
__device__ __align__(16) __half g_pl[4][(size_t)B_ * L_ * D_];

// ---------------------------------------------------------------------------
DEVINL void cp_async16(uint32_t dst, const void* src) {
    asm volatile("cp.async.cg.shared.global [%0], [%1], 16;" :: "r"(dst), "l"(src) : "memory");
}
DEVINL void cp_commit() { asm volatile("cp.async.commit_group;" ::: "memory"); }
template <int N>
DEVINL void cp_wait_group() { asm volatile("cp.async.wait_group %0;" :: "n"(N) : "memory"); }
DEVINL uint32_t smem_u32(const void* p) {
    uint32_t a;
    asm("{ .reg .u64 t; cvta.to.shared.u64 t, %1; cvt.u32.u64 %0, t; }" : "=r"(a) : "l"(p));
    return a;
}

// bf16 split (proj-internal MMA tiles)
DEVINL uint32_t pack2b(__nv_bfloat16 a, __nv_bfloat16 b) {
    return (uint32_t)__bfloat16_as_ushort(a) | ((uint32_t)__bfloat16_as_ushort(b) << 16);
}
DEVINL void split2(float a, float b, uint32_t& h, uint32_t& l) {
    __nv_bfloat16 ha = __float2bfloat16_rn(a);
    __nv_bfloat16 hb = __float2bfloat16_rn(b);
    __nv_bfloat16 la = __float2bfloat16_rn(a - __bfloat162float(ha));
    __nv_bfloat16 lb = __float2bfloat16_rn(b - __bfloat162float(hb));
    h = pack2b(ha, hb);
    l = pack2b(la, lb);
}
// fp16 split (scratch)
DEVINL uint32_t pack2h(__half a, __half b) {
    return (uint32_t)__half_as_ushort(a) | ((uint32_t)__half_as_ushort(b) << 16);
}
DEVINL void split2h(float a, float b, uint32_t& h, uint32_t& l) {
    __half ha = __float2half_rn(a);
    __half hb = __float2half_rn(b);
    __half la = __float2half_rn(a - __half2float(ha));
    __half lb = __float2half_rn(b - __half2float(hb));
    h = pack2h(ha, hb);
    l = pack2h(la, lb);
}

// HW tanh: single MUFU.TANH, abs err ~2^-11
DEVINL float tanh_hw(float x) {
    float r;
    asm("tanh.approx.f32 %0, %1;" : "=f"(r) : "f"(x));
    return r;
}

// Load ROWS x 128 16-bit tile (row-major 256B rows) into padded smem (272B rows).
template <int ROWS, int THREADS>
DEVINL void load_tile_cp(uint32_t dst, const void* src, int tid) {
    const char* s = reinterpret_cast<const char*>(src);
#pragma unroll
    for (int i = 0; i < ROWS * 16 / THREADS; i++) {
        int idx = i * THREADS + tid;
        int r = idx >> 4, c = idx & 15;
        cp_async16(dst + r * 272 + c * 16, s + r * 256 + c * 16);
    }
}

typedef wmma::fragment<wmma::matrix_a, 16, 16, 16, __nv_bfloat16, wmma::row_major> FragAb;
typedef wmma::fragment<wmma::matrix_b, 16, 16, 16, __nv_bfloat16, wmma::row_major> FragBrb;
typedef wmma::fragment<wmma::matrix_a, 16, 16, 16, __half, wmma::row_major> FragAh;
typedef wmma::fragment<wmma::matrix_b, 16, 16, 16, __half, wmma::col_major> FragBch;
typedef wmma::fragment<wmma::accumulator, 16, 16, 16, float> FragC;

// ---------------------------------------------------------------------------
// Kernel 1: projections Y = X @ W + b.  3-pass bf16 MMA, fp16 hi/lo output.
// CTA: 64-row X tile, 8 warps in 2x4 grid (32x32 each), 2 CTAs/SM.
// ---------------------------------------------------------------------------
__global__ __launch_bounds__(PT, 2)
void proj_kernel(const float* __restrict__ query, const float* __restrict__ key,
                 const float* __restrict__ wqm, const float* __restrict__ bqm,
                 const float* __restrict__ wkm, const float* __restrict__ bkm,
                 const float* __restrict__ wqs, const float* __restrict__ bqs,
                 const float* __restrict__ wks, const float* __restrict__ bks) {
    extern __shared__ __align__(16) char smem[];
    const int tid = threadIdx.x, wid = tid >> 5;
    const int p = blockIdx.y;
    const int m0 = blockIdx.x * 64;

    const float* src  = (p & 1) ? key : query;
    const float* W    = (p == 0) ? wqm : (p == 1) ? wkm : (p == 2) ? wqs : wks;
    const float* bias = (p == 0) ? bqm : (p == 1) ? bkm : (p == 2) ? bqs : bks;

    float* sbias = reinterpret_cast<float*>(smem + P_BIAS);
    if (tid < 128) sbias[tid] = bias[tid];

    // X (64x128): f32 -> bf16 hi/lo split
#pragma unroll
    for (int i = 0; i < 4; i++) {
        int idx = i * PT + tid;
        int r = idx >> 4, c = idx & 15;
        const float* sp = src + (size_t)(m0 + r) * D_ + c * 8;
        float4 v0 = *reinterpret_cast<const float4*>(sp);
        float4 v1 = *reinterpret_cast<const float4*>(sp + 4);
        uint4 H, Lo;
        split2(v0.x, v0.y, H.x, Lo.x);
        split2(v0.z, v0.w, H.y, Lo.y);
        split2(v1.x, v1.y, H.z, Lo.z);
        split2(v1.z, v1.w, H.w, Lo.w);
        *reinterpret_cast<uint4*>(smem + P_XH + r * 272 + c * 16) = H;
        *reinterpret_cast<uint4*>(smem + P_XL + r * 272 + c * 16) = Lo;
    }
    // W (128x128): f32 -> bf16 hi/lo split
#pragma unroll
    for (int i = 0; i < 8; i++) {
        int idx = i * PT + tid;
        int r = idx >> 4, c = idx & 15;
        const float* sp = W + (size_t)r * D_ + c * 8;
        float4 v0 = *reinterpret_cast<const float4*>(sp);
        float4 v1 = *reinterpret_cast<const float4*>(sp + 4);
        uint4 H, Lo;
        split2(v0.x, v0.y, H.x, Lo.x);
        split2(v0.z, v0.w, H.y, Lo.y);
        split2(v1.x, v1.y, H.z, Lo.z);
        split2(v1.z, v1.w, H.w, Lo.w);
        *reinterpret_cast<uint4*>(smem + P_WH + r * 272 + c * 16) = H;
        *reinterpret_cast<uint4*>(smem + P_WL + r * 272 + c * 16) = Lo;
    }
    __syncthreads();

    const int wm = wid & 1, wn = wid >> 1;   // 2 x 4 warp grid -> 32 x 32 each
    const __nv_bfloat16* sXh = reinterpret_cast<const __nv_bfloat16*>(smem + P_XH);
    const __nv_bfloat16* sXl = reinterpret_cast<const __nv_bfloat16*>(smem + P_XL);
    const __nv_bfloat16* sWh = reinterpret_cast<const __nv_bfloat16*>(smem + P_WH);
    const __nv_bfloat16* sWl = reinterpret_cast<const __nv_bfloat16*>(smem + P_WL);

    FragC acc[2][2];
#pragma unroll
    for (int i = 0; i < 2; i++)
#pragma unroll
        for (int j = 0; j < 2; j++) wmma::fill_fragment(acc[i][j], 0.0f);

#pragma unroll
    for (int k = 0; k < 8; k++) {
        FragAb ah[2], al[2];
        wmma::load_matrix_sync(ah[0], sXh + (wm * 32 + 0) * LDB + k * 16, LDB);
        wmma::load_matrix_sync(ah[1], sXh + (wm * 32 + 16) * LDB + k * 16, LDB);
        wmma::load_matrix_sync(al[0], sXl + (wm * 32 + 0) * LDB + k * 16, LDB);
        wmma::load_matrix_sync(al[1], sXl + (wm * 32 + 16) * LDB + k * 16, LDB);
#pragma unroll
        for (int j = 0; j < 2; j++) {
            FragBrb bh, bl;
            wmma::load_matrix_sync(bh, sWh + (k * 16) * LDB + (wn * 32 + j * 16), LDB);
            wmma::load_matrix_sync(bl, sWl + (k * 16) * LDB + (wn * 32 + j * 16), LDB);
            wmma::mma_sync(acc[0][j], ah[0], bh, acc[0][j]);
            wmma::mma_sync(acc[1][j], ah[1], bh, acc[1][j]);
            wmma::mma_sync(acc[0][j], al[0], bh, acc[0][j]);
            wmma::mma_sync(acc[1][j], al[1], bh, acc[1][j]);
            wmma::mma_sync(acc[0][j], ah[0], bl, acc[0][j]);
            wmma::mma_sync(acc[1][j], ah[1], bl, acc[1][j]);
        }
    }
    __syncthreads();

    // C -> smem overlay (X area no longer needed)
    float* Cs = reinterpret_cast<float*>(smem + P_C);
#pragma unroll
    for (int i = 0; i < 2; i++)
#pragma unroll
        for (int j = 0; j < 2; j++)
            wmma::store_matrix_sync(Cs + (wm * 32 + i * 16) * LDC + (wn * 32 + j * 16),
                                    acc[i][j], LDC, wmma::mem_row_major);
    __syncthreads();

    // epilogue: + bias, fp16 hi/lo split, store scratch (64 rows)
#pragma unroll
    for (int i = 0; i < 8; i++) {
        int u = i * PT + tid;
        int r = u >> 5, c4 = (u & 31) << 2;
        float4 v = *reinterpret_cast<const float4*>(Cs + r * LDC + c4);
        v.x += sbias[c4 + 0];
        v.y += sbias[c4 + 1];
        v.z += sbias[c4 + 2];
        v.w += sbias[c4 + 3];
        uint32_t h01, l01, h23, l23;
        split2h(v.x, v.y, h01, l01);
        split2h(v.z, v.w, h23, l23);
        size_t o = (size_t)(m0 + r) * D_ + c4;
        *reinterpret_cast<uint2*>(g_ph[p] + o) = make_uint2(h01, h23);
        *reinterpret_cast<uint2*>(g_pl[p] + o) = make_uint2(l01, l23);
    }
}

// ---------------------------------------------------------------------------
// Kernel 2: scores. CTA = 128x128 S tile, both phases unrolled. fp16 2-pass:
// S = (Qh + Ql) @ Kh^T. All 6 tiles resident; ONE barrier, then barrier-free.
// Epilogue: FMUL -> MUFU.TANH -> FFMA -> select -> store.
// ---------------------------------------------------------------------------
__global__ __launch_bounds__(NT, 1)
void scores_kernel(const int* __restrict__ mask, float* __restrict__ out) {
    extern __shared__ __align__(16) char smem[];
    const int tid = threadIdx.x, wid = tid >> 5;
    const int nb0 = blockIdx.x * 128;
    const int mb0 = blockIdx.y * 128;
    const int b = blockIdx.z;
    const uint32_t sbase = smem_u32(smem);
    const int wm = wid & 3, wn = wid >> 2;   // 4 x 4 -> 32 x 32 per warp
    const float inv_sqrt_d = 0.08838834764831845f;

    const size_t qoff = ((size_t)b * L_ + mb0) * D_;
    const size_t koff = ((size_t)b * L_ + nb0) * D_;

    // g0: Q0h, Q0l, K0h, Q1h
    load_tile_cp<128, NT>(sbase + S0, g_ph[0] + qoff, tid);
    load_tile_cp<128, NT>(sbase + S1, g_pl[0] + qoff, tid);
    load_tile_cp<128, NT>(sbase + S2, g_ph[1] + koff, tid);
    load_tile_cp<128, NT>(sbase + S3, g_ph[2] + qoff, tid);
    cp_commit();

    // mask -> f32 staging over S4/S5 -> per-lane bitmask
    float* Ms = reinterpret_cast<float*>(smem + S4);
#pragma unroll
    for (int i = 0; i < 8; i++) {
        int u = i * NT + tid;
        int r = u >> 5, c4 = (u & 31) << 2;
        int4 mm = *reinterpret_cast<const int4*>(
            mask + ((size_t)b * L_ + mb0 + r) * L_ + nb0 + c4);
        float4 f;
        f.x = mm.x ? 1.0f : 0.0f;
        f.y = mm.y ? 1.0f : 0.0f;
        f.z = mm.z ? 1.0f : 0.0f;
        f.w = mm.w ? 1.0f : 0.0f;
        *reinterpret_cast<float4*>(Ms + r * LDC + c4) = f;
    }
    __syncthreads();

    uint32_t mbits = 0;
#pragma unroll
    for (int i = 0; i < 2; i++)
#pragma unroll
        for (int j = 0; j < 2; j++) {
            FragC mf;
            wmma::load_matrix_sync(mf, Ms + (wm * 32 + i * 16) * LDC + (wn * 32 + j * 16),
                                   LDC, wmma::mem_row_major);
#pragma unroll
            for (int e = 0; e < 8; e++)
                mbits |= (mf.x[e] != 0.0f ? 1u : 0u) << ((i * 2 + j) * 8 + e);
        }
    __syncthreads();   // staging consumed; S4/S5 reusable

    // g1: Q1l, K1h
    load_tile_cp<128, NT>(sbase + S4, g_pl[2] + qoff, tid);
    load_tile_cp<128, NT>(sbase + S5, g_ph[3] + koff, tid);
    cp_commit();

    cp_wait_group<0>();
    __syncthreads();   // ONLY barrier before compute

#pragma unroll
    for (int phase = 0; phase < 2; phase++) {
        const __half* Qh = reinterpret_cast<const __half*>(smem + (phase ? S3 : S0));
        const __half* Ql = reinterpret_cast<const __half*>(smem + (phase ? S4 : S1));
        const __half* Kh = reinterpret_cast<const __half*>(smem + (phase ? S5 : S2));

        FragC acc[2][2];
#pragma unroll
        for (int i = 0; i < 2; i++)
#pragma unroll
            for (int j = 0; j < 2; j++) wmma::fill_fragment(acc[i][j], 0.0f);

#pragma unroll
        for (int k = 0; k < 8; k++) {
            FragAh ah[2], al[2];
            wmma::load_matrix_sync(ah[0], Qh + (wm * 32 + 0) * LDB + k * 16, LDB);
            wmma::load_matrix_sync(ah[1], Qh + (wm * 32 + 16) * LDB + k * 16, LDB);
            wmma::load_matrix_sync(al[0], Ql + (wm * 32 + 0) * LDB + k * 16, LDB);
            wmma::load_matrix_sync(al[1], Ql + (wm * 32 + 16) * LDB + k * 16, LDB);
#pragma unroll
            for (int j = 0; j < 2; j++) {
                FragBch bh;   // K row-major [n][k] == col-major (k,n)
                wmma::load_matrix_sync(bh, Kh + (wn * 32 + j * 16) * LDB + k * 16, LDB);
                wmma::mma_sync(acc[0][j], ah[0], bh, acc[0][j]);
                wmma::mma_sync(acc[1][j], ah[1], bh, acc[1][j]);
                wmma::mma_sync(acc[0][j], al[0], bh, acc[0][j]);
                wmma::mma_sync(acc[1][j], al[1], bh, acc[1][j]);
            }
        }

        // epilogue (phase is compile-time): FMUL -> MUFU.TANH -> FFMA -> sel -> STG
        const float sA = phase ? 4.0f : 0.5f;
        const float sB = phase ? -6.0f : 0.5f;
        const float sC = phase ? -10.0f : 0.0f;
        float* obase = out + (size_t)phase * B_ * L_ * L_ + (size_t)b * L_ * L_;
#pragma unroll
        for (int i = 0; i < 2; i++) {
#pragma unroll
            for (int j = 0; j < 2; j++) {
                int r0 = wm * 32 + i * 16, c0 = wn * 32 + j * 16;
#pragma unroll
                for (int e = 0; e < 8; e++) {
                    float t = tanh_hw(acc[i][j].x[e] * inv_sqrt_d);
                    bool m = (mbits >> ((i * 2 + j) * 8 + e)) & 1u;
                    acc[i][j].x[e] = m ? fmaf(sA, t, sB) : sC;
                }
                wmma::store_matrix_sync(obase + (size_t)(mb0 + r0) * L_ + (nb0 + c0),
                                        acc[i][j], L_, wmma::mem_row_major);
            }
        }
        // no barrier: phase-1 tiles are distinct slots, all preloaded
    }
}

// ---------------------------------------------------------------------------
extern "C" void kernel_launch(void* const* d_in, const int* in_sizes, int n_in,
                              void* d_out, int out_size) {
    const float* query = (const float*)d_in[0];
    const float* key   = (const float*)d_in[1];
    const int*   mask  = (const int*)d_in[2];
    const float* wqm = (const float*)d_in[3];
    const float* bqm = (const float*)d_in[4];
    const float* wkm = (const float*)d_in[5];
    const float* bkm = (const float*)d_in[6];
    const float* wqs = (const float*)d_in[7];
    const float* bqs = (const float*)d_in[8];
    const float* wks = (const float*)d_in[9];
    const float* bks = (const float*)d_in[10];
    float* out = (float*)d_out;

    cudaFuncSetAttribute(proj_kernel, cudaFuncAttributeMaxDynamicSharedMemorySize, P_SMEM);
    cudaFuncSetAttribute(scores_kernel, cudaFuncAttributeMaxDynamicSharedMemorySize, S_SMEM);

    proj_kernel<<<dim3((B_ * L_) / 64, 4), PT, P_SMEM>>>(
        query, key, wqm, bqm, wkm, bkm, wqs, bqs, wks, bks);
    scores_kernel<<<dim3(L_ / 128, L_ / 128, B_), NT, S_SMEM>>>(mask, out);
}

// round 12
// speedup vs baseline: 1.4130x; 1.0732x over previous
#include <cuda_runtime.h>
#include <cuda_bf16.h>
#include <cuda_fp16.h>
#include <mma.h>
#include <cstdint>

using namespace nvcuda;

#define DEVINL __device__ __forceinline__

static constexpr int B_ = 8;
static constexpr int L_ = 2048;
static constexpr int D_ = 128;
static constexpr int NT = 256;    // scores threads (8 warps)
static constexpr int PT = 256;    // proj threads (8 warps)

// Padded strides (elements)
static constexpr int LDB = 136;   // 16-bit tiles: 272B rows
static constexpr int LDC = 132;   // f32 staging rows

static constexpr int TILE_BYTES = 128 * LDB * 2;    // 34816
static constexpr int TILE64_BYTES = 64 * LDB * 2;   // 17408

// ---- scores kernel smem: 3 tile slots (104448 B), 2 CTAs/SM ----
// S0=Qh S1=Ql S2=Kh  (fp16). Mask f32 staging overlays S0..S1 (67584<=69632).
static constexpr int S0 = 0;
static constexpr int S1 = S0 + TILE_BYTES;
static constexpr int S2 = S1 + TILE_BYTES;
static constexpr int S_SMEM = S2 + TILE_BYTES;      // 104448 (x2 <= 228KB)

// ---- proj kernel smem (64-row X tile, 2 CTAs/SM) ----
static constexpr int P_XH = 0;                      // 64-row tile
static constexpr int P_XL = P_XH + TILE64_BYTES;
static constexpr int P_WH = P_XL + TILE64_BYTES;    // 128-row tile
static constexpr int P_WL = P_WH + TILE_BYTES;
static constexpr int P_BIAS = P_WL + TILE_BYTES;    // 104448
static constexpr int P_SMEM = P_BIAS + 512;         // 104960
static constexpr int P_C = P_XH;                    // overlay: 33792 <= 34816

// ---------------------------------------------------------------------------
// Scratch: projection outputs fp16 hi/lo (p: qm=0, km=1, qs=2, ks=3)
// ---------------------------------------------------------------------------
__device__ __align__(16) __half g_ph[4][(size_t)B_ * L_ * D_];
__device__ __align__(16) __half g_pl[4][(size_t)B_ * L_ * D_];

// ---------------------------------------------------------------------------
DEVINL void cp_async16(uint32_t dst, const void* src) {
    asm volatile("cp.async.cg.shared.global [%0], [%1], 16;" :: "r"(dst), "l"(src) : "memory");
}
DEVINL void cp_commit() { asm volatile("cp.async.commit_group;" ::: "memory"); }
template <int N>
DEVINL void cp_wait_group() { asm volatile("cp.async.wait_group %0;" :: "n"(N) : "memory"); }
DEVINL uint32_t smem_u32(const void* p) {
    uint32_t a;
    asm("{ .reg .u64 t; cvta.to.shared.u64 t, %1; cvt.u32.u64 %0, t; }" : "=r"(a) : "l"(p));
    return a;
}

// bf16 split (proj-internal MMA tiles)
DEVINL uint32_t pack2b(__nv_bfloat16 a, __nv_bfloat16 b) {
    return (uint32_t)__bfloat16_as_ushort(a) | ((uint32_t)__bfloat16_as_ushort(b) << 16);
}
DEVINL void split2(float a, float b, uint32_t& h, uint32_t& l) {
    __nv_bfloat16 ha = __float2bfloat16_rn(a);
    __nv_bfloat16 hb = __float2bfloat16_rn(b);
    __nv_bfloat16 la = __float2bfloat16_rn(a - __bfloat162float(ha));
    __nv_bfloat16 lb = __float2bfloat16_rn(b - __bfloat162float(hb));
    h = pack2b(ha, hb);
    l = pack2b(la, lb);
}
// fp16 split (scratch)
DEVINL uint32_t pack2h(__half a, __half b) {
    return (uint32_t)__half_as_ushort(a) | ((uint32_t)__half_as_ushort(b) << 16);
}
DEVINL void split2h(float a, float b, uint32_t& h, uint32_t& l) {
    __half ha = __float2half_rn(a);
    __half hb = __float2half_rn(b);
    __half la = __float2half_rn(a - __half2float(ha));
    __half lb = __float2half_rn(b - __half2float(hb));
    h = pack2h(ha, hb);
    l = pack2h(la, lb);
}

// HW tanh: single MUFU.TANH, abs err ~2^-11
DEVINL float tanh_hw(float x) {
    float r;
    asm("tanh.approx.f32 %0, %1;" : "=f"(r) : "f"(x));
    return r;
}

// Load ROWS x 128 16-bit tile (row-major 256B rows) into padded smem (272B rows).
template <int ROWS, int THREADS>
DEVINL void load_tile_cp(uint32_t dst, const void* src, int tid) {
    const char* s = reinterpret_cast<const char*>(src);
#pragma unroll
    for (int i = 0; i < ROWS * 16 / THREADS; i++) {
        int idx = i * THREADS + tid;
        int r = idx >> 4, c = idx & 15;
        cp_async16(dst + r * 272 + c * 16, s + r * 256 + c * 16);
    }
}

typedef wmma::fragment<wmma::matrix_a, 16, 16, 16, __nv_bfloat16, wmma::row_major> FragAb;
typedef wmma::fragment<wmma::matrix_b, 16, 16, 16, __nv_bfloat16, wmma::row_major> FragBrb;
typedef wmma::fragment<wmma::matrix_a, 16, 16, 16, __half, wmma::row_major> FragAh;
typedef wmma::fragment<wmma::matrix_b, 16, 16, 16, __half, wmma::col_major> FragBch;
typedef wmma::fragment<wmma::accumulator, 16, 16, 16, float> FragC;

// ---------------------------------------------------------------------------
// Kernel 1: projections Y = X @ W + b.  3-pass bf16 MMA, fp16 hi/lo output.
// CTA: 64-row X tile, 8 warps in 2x4 grid (32x32 each), 2 CTAs/SM.
// ---------------------------------------------------------------------------
__global__ __launch_bounds__(PT, 2)
void proj_kernel(const float* __restrict__ query, const float* __restrict__ key,
                 const float* __restrict__ wqm, const float* __restrict__ bqm,
                 const float* __restrict__ wkm, const float* __restrict__ bkm,
                 const float* __restrict__ wqs, const float* __restrict__ bqs,
                 const float* __restrict__ wks, const float* __restrict__ bks) {
    extern __shared__ __align__(16) char smem[];
    const int tid = threadIdx.x, wid = tid >> 5;
    const int p = blockIdx.y;
    const int m0 = blockIdx.x * 64;

    const float* src  = (p & 1) ? key : query;
    const float* W    = (p == 0) ? wqm : (p == 1) ? wkm : (p == 2) ? wqs : wks;
    const float* bias = (p == 0) ? bqm : (p == 1) ? bkm : (p == 2) ? bqs : bks;

    float* sbias = reinterpret_cast<float*>(smem + P_BIAS);
    if (tid < 128) sbias[tid] = bias[tid];

    // X (64x128): f32 -> bf16 hi/lo split
#pragma unroll
    for (int i = 0; i < 4; i++) {
        int idx = i * PT + tid;
        int r = idx >> 4, c = idx & 15;
        const float* sp = src + (size_t)(m0 + r) * D_ + c * 8;
        float4 v0 = *reinterpret_cast<const float4*>(sp);
        float4 v1 = *reinterpret_cast<const float4*>(sp + 4);
        uint4 H, Lo;
        split2(v0.x, v0.y, H.x, Lo.x);
        split2(v0.z, v0.w, H.y, Lo.y);
        split2(v1.x, v1.y, H.z, Lo.z);
        split2(v1.z, v1.w, H.w, Lo.w);
        *reinterpret_cast<uint4*>(smem + P_XH + r * 272 + c * 16) = H;
        *reinterpret_cast<uint4*>(smem + P_XL + r * 272 + c * 16) = Lo;
    }
    // W (128x128): f32 -> bf16 hi/lo split
#pragma unroll
    for (int i = 0; i < 8; i++) {
        int idx = i * PT + tid;
        int r = idx >> 4, c = idx & 15;
        const float* sp = W + (size_t)r * D_ + c * 8;
        float4 v0 = *reinterpret_cast<const float4*>(sp);
        float4 v1 = *reinterpret_cast<const float4*>(sp + 4);
        uint4 H, Lo;
        split2(v0.x, v0.y, H.x, Lo.x);
        split2(v0.z, v0.w, H.y, Lo.y);
        split2(v1.x, v1.y, H.z, Lo.z);
        split2(v1.z, v1.w, H.w, Lo.w);
        *reinterpret_cast<uint4*>(smem + P_WH + r * 272 + c * 16) = H;
        *reinterpret_cast<uint4*>(smem + P_WL + r * 272 + c * 16) = Lo;
    }
    __syncthreads();

    const int wm = wid & 1, wn = wid >> 1;   // 2 x 4 warp grid -> 32 x 32 each
    const __nv_bfloat16* sXh = reinterpret_cast<const __nv_bfloat16*>(smem + P_XH);
    const __nv_bfloat16* sXl = reinterpret_cast<const __nv_bfloat16*>(smem + P_XL);
    const __nv_bfloat16* sWh = reinterpret_cast<const __nv_bfloat16*>(smem + P_WH);
    const __nv_bfloat16* sWl = reinterpret_cast<const __nv_bfloat16*>(smem + P_WL);

    FragC acc[2][2];
#pragma unroll
    for (int i = 0; i < 2; i++)
#pragma unroll
        for (int j = 0; j < 2; j++) wmma::fill_fragment(acc[i][j], 0.0f);

#pragma unroll
    for (int k = 0; k < 8; k++) {
        FragAb ah[2], al[2];
        wmma::load_matrix_sync(ah[0], sXh + (wm * 32 + 0) * LDB + k * 16, LDB);
        wmma::load_matrix_sync(ah[1], sXh + (wm * 32 + 16) * LDB + k * 16, LDB);
        wmma::load_matrix_sync(al[0], sXl + (wm * 32 + 0) * LDB + k * 16, LDB);
        wmma::load_matrix_sync(al[1], sXl + (wm * 32 + 16) * LDB + k * 16, LDB);
#pragma unroll
        for (int j = 0; j < 2; j++) {
            FragBrb bh, bl;
            wmma::load_matrix_sync(bh, sWh + (k * 16) * LDB + (wn * 32 + j * 16), LDB);
            wmma::load_matrix_sync(bl, sWl + (k * 16) * LDB + (wn * 32 + j * 16), LDB);
            wmma::mma_sync(acc[0][j], ah[0], bh, acc[0][j]);
            wmma::mma_sync(acc[1][j], ah[1], bh, acc[1][j]);
            wmma::mma_sync(acc[0][j], al[0], bh, acc[0][j]);
            wmma::mma_sync(acc[1][j], al[1], bh, acc[1][j]);
            wmma::mma_sync(acc[0][j], ah[0], bl, acc[0][j]);
            wmma::mma_sync(acc[1][j], ah[1], bl, acc[1][j]);
        }
    }
    __syncthreads();

    // C -> smem overlay (X area no longer needed)
    float* Cs = reinterpret_cast<float*>(smem + P_C);
#pragma unroll
    for (int i = 0; i < 2; i++)
#pragma unroll
        for (int j = 0; j < 2; j++)
            wmma::store_matrix_sync(Cs + (wm * 32 + i * 16) * LDC + (wn * 32 + j * 16),
                                    acc[i][j], LDC, wmma::mem_row_major);
    __syncthreads();

    // epilogue: + bias, fp16 hi/lo split, store scratch (64 rows)
#pragma unroll
    for (int i = 0; i < 8; i++) {
        int u = i * PT + tid;
        int r = u >> 5, c4 = (u & 31) << 2;
        float4 v = *reinterpret_cast<const float4*>(Cs + r * LDC + c4);
        v.x += sbias[c4 + 0];
        v.y += sbias[c4 + 1];
        v.z += sbias[c4 + 2];
        v.w += sbias[c4 + 3];
        uint32_t h01, l01, h23, l23;
        split2h(v.x, v.y, h01, l01);
        split2h(v.z, v.w, h23, l23);
        size_t o = (size_t)(m0 + r) * D_ + c4;
        *reinterpret_cast<uint2*>(g_ph[p] + o) = make_uint2(h01, h23);
        *reinterpret_cast<uint2*>(g_pl[p] + o) = make_uint2(l01, l23);
    }
}

// ---------------------------------------------------------------------------
// Kernel 2: scores. CTA = 128x128 S tile for ONE phase (mean or std).
// 2 CTAs/SM -> cross-CTA overlap of loads/MMA/epilogue. 8 warps, 4x2 grid,
// 32x64 per warp. fp16 2-pass: S = (Qh + Ql) @ Kh^T.
//   g0: Kh -> S2 (overlaps mask staging/bit conversion in S0/S1)
//   g1: Qh -> S0, Ql -> S1
//   one wait + barrier, then barrier-free MMA + epilogue.
// ---------------------------------------------------------------------------
__global__ __launch_bounds__(NT, 2)
void scores_kernel(const int* __restrict__ mask, float* __restrict__ out) {
    extern __shared__ __align__(16) char smem[];
    const int tid = threadIdx.x, wid = tid >> 5;
    const int nb0 = blockIdx.x * 128;
    const int mb0 = blockIdx.y * 128;
    const int b = blockIdx.z >> 1;
    const int phase = blockIdx.z & 1;
    const uint32_t sbase = smem_u32(smem);
    const int wm = wid & 3, wn = wid >> 2;   // 4 x 2 -> 32 x 64 per warp
    const float inv_sqrt_d = 0.08838834764831845f;

    const size_t qoff = ((size_t)b * L_ + mb0) * D_;
    const size_t koff = ((size_t)b * L_ + nb0) * D_;
    const int pq = 2 * phase, pk = 2 * phase + 1;

    // g0: Kh
    load_tile_cp<128, NT>(sbase + S2, g_ph[pk] + koff, tid);
    cp_commit();

    // mask -> f32 staging over S0/S1 -> per-lane bitmask
    float* Ms = reinterpret_cast<float*>(smem + S0);
#pragma unroll
    for (int i = 0; i < 16; i++) {
        int u = i * NT + tid;
        int r = u >> 5, c4 = (u & 31) << 2;
        int4 mm = *reinterpret_cast<const int4*>(
            mask + ((size_t)b * L_ + mb0 + r) * L_ + nb0 + c4);
        float4 f;
        f.x = mm.x ? 1.0f : 0.0f;
        f.y = mm.y ? 1.0f : 0.0f;
        f.z = mm.z ? 1.0f : 0.0f;
        f.w = mm.w ? 1.0f : 0.0f;
        *reinterpret_cast<float4*>(Ms + r * LDC + c4) = f;
    }
    __syncthreads();

    uint32_t mbits[2] = {0u, 0u};
#pragma unroll
    for (int i = 0; i < 2; i++)
#pragma unroll
        for (int j = 0; j < 4; j++) {
            FragC mf;
            wmma::load_matrix_sync(mf, Ms + (wm * 32 + i * 16) * LDC + (wn * 64 + j * 16),
                                   LDC, wmma::mem_row_major);
#pragma unroll
            for (int e = 0; e < 8; e++)
                mbits[i] |= (mf.x[e] != 0.0f ? 1u : 0u) << (j * 8 + e);
        }
    __syncthreads();   // staging consumed; S0/S1 reusable

    // g1: Qh, Ql
    load_tile_cp<128, NT>(sbase + S0, g_ph[pq] + qoff, tid);
    load_tile_cp<128, NT>(sbase + S1, g_pl[pq] + qoff, tid);
    cp_commit();

    cp_wait_group<0>();
    __syncthreads();   // ONLY barrier before compute

    const __half* Qh = reinterpret_cast<const __half*>(smem + S0);
    const __half* Ql = reinterpret_cast<const __half*>(smem + S1);
    const __half* Kh = reinterpret_cast<const __half*>(smem + S2);

    FragC acc[2][4];
#pragma unroll
    for (int i = 0; i < 2; i++)
#pragma unroll
        for (int j = 0; j < 4; j++) wmma::fill_fragment(acc[i][j], 0.0f);

#pragma unroll
    for (int k = 0; k < 8; k++) {
        FragAh ah[2], al[2];
        wmma::load_matrix_sync(ah[0], Qh + (wm * 32 + 0) * LDB + k * 16, LDB);
        wmma::load_matrix_sync(ah[1], Qh + (wm * 32 + 16) * LDB + k * 16, LDB);
        wmma::load_matrix_sync(al[0], Ql + (wm * 32 + 0) * LDB + k * 16, LDB);
        wmma::load_matrix_sync(al[1], Ql + (wm * 32 + 16) * LDB + k * 16, LDB);
#pragma unroll
        for (int j = 0; j < 4; j++) {
            FragBch bh;   // K row-major [n][k] == col-major (k,n)
            wmma::load_matrix_sync(bh, Kh + (wn * 64 + j * 16) * LDB + k * 16, LDB);
            wmma::mma_sync(acc[0][j], ah[0], bh, acc[0][j]);
            wmma::mma_sync(acc[1][j], ah[1], bh, acc[1][j]);
            wmma::mma_sync(acc[0][j], al[0], bh, acc[0][j]);
            wmma::mma_sync(acc[1][j], al[1], bh, acc[1][j]);
        }
    }

    // epilogue: FMUL -> MUFU.TANH -> FFMA -> select -> store
    const float sA = phase ? 4.0f : 0.5f;
    const float sB = phase ? -6.0f : 0.5f;
    const float sC = phase ? -10.0f : 0.0f;
    float* obase = out + (size_t)phase * B_ * L_ * L_ + (size_t)b * L_ * L_;
#pragma unroll
    for (int i = 0; i < 2; i++) {
#pragma unroll
        for (int j = 0; j < 4; j++) {
            int r0 = wm * 32 + i * 16, c0 = wn * 64 + j * 16;
#pragma unroll
            for (int e = 0; e < 8; e++) {
                float t = tanh_hw(acc[i][j].x[e] * inv_sqrt_d);
                bool m = (mbits[i] >> (j * 8 + e)) & 1u;
                acc[i][j].x[e] = m ? fmaf(sA, t, sB) : sC;
            }
            wmma::store_matrix_sync(obase + (size_t)(mb0 + r0) * L_ + (nb0 + c0),
                                    acc[i][j], L_, wmma::mem_row_major);
        }
    }
}

// ---------------------------------------------------------------------------
extern "C" void kernel_launch(void* const* d_in, const int* in_sizes, int n_in,
                              void* d_out, int out_size) {
    const float* query = (const float*)d_in[0];
    const float* key   = (const float*)d_in[1];
    const int*   mask  = (const int*)d_in[2];
    const float* wqm = (const float*)d_in[3];
    const float* bqm = (const float*)d_in[4];
    const float* wkm = (const float*)d_in[5];
    const float* bkm = (const float*)d_in[6];
    const float* wqs = (const float*)d_in[7];
    const float* bqs = (const float*)d_in[8];
    const float* wks = (const float*)d_in[9];
    const float* bks = (const float*)d_in[10];
    float* out = (float*)d_out;

    cudaFuncSetAttribute(proj_kernel, cudaFuncAttributeMaxDynamicSharedMemorySize, P_SMEM);
    cudaFuncSetAttribute(scores_kernel, cudaFuncAttributeMaxDynamicSharedMemorySize, S_SMEM);

    proj_kernel<<<dim3((B_ * L_) / 64, 4), PT, P_SMEM>>>(
        query, key, wqm, bqm, wkm, bkm, wqs, bqs, wks, bks);
    scores_kernel<<<dim3(L_ / 128, L_ / 128, 2 * B_), NT, S_SMEM>>>(mask, out);
}